// round 13
// baseline (speedup 1.0000x reference)
#include <cuda_runtime.h>
#include <cuda_fp16.h>
#include <math.h>
#include <stdint.h>

// ---------------------------------------------------------------------------
// TransformerBlock: B=4, N=1024, D=768, H=12, d=64, D_FF=3072
// Round 13 (= round 11 resubmit; repeated infra failures): round 10
// (validated, 381us) +
//   - flash v2: 128-row Q tiles, cp.async double-buffered K/V (overlap)
//   - single merged f2h weight-conversion launch (was 6)
// ---------------------------------------------------------------------------

#define BATCH     4
#define SEQ       1024
#define DIM       768
#define HEADS     12
#define HDIM      64
#define DFF       3072
#define TOKENS    (BATCH * SEQ)      // 4096
#define LN_EPS    1e-6f

// -------------------- scratch (no allocation allowed) ----------------------
__device__ __half g_xnh [TOKENS * DIM];
__device__ __half g_qh  [TOKENS * DIM];
__device__ __half g_kh  [TOKENS * DIM];
__device__ __half g_vh  [TOKENS * DIM];
__device__ __half g_ctxh[TOKENS * DIM];
__device__ float  g_x1  [TOKENS * DIM];
__device__ __half g_xn2h[TOKENS * DIM];
__device__ __half g_h1h [TOKENS * DFF];
// fp16 weight copies (converted once per launch)
__device__ __half g_Wqh[DIM * DIM];
__device__ __half g_Wkh[DIM * DIM];
__device__ __half g_Wvh[DIM * DIM];
__device__ __half g_Woh[DIM * DIM];
__device__ __half g_W1h[DIM * DFF];
__device__ __half g_W2h[DFF * DIM];

// ---------------------------- helpers --------------------------------------
__device__ __forceinline__ uint32_t smem_u32(const void* p) {
    uint32_t a;
    asm("{ .reg .u64 t; cvta.to.shared.u64 t, %1; cvt.u32.u64 %0, t; }" : "=r"(a) : "l"(p));
    return a;
}
__device__ __forceinline__ void ldsm_x4(uint32_t& r0, uint32_t& r1, uint32_t& r2,
                                        uint32_t& r3, uint32_t addr) {
    asm volatile("ldmatrix.sync.aligned.m8n8.x4.shared.b16 {%0,%1,%2,%3}, [%4];"
                 : "=r"(r0), "=r"(r1), "=r"(r2), "=r"(r3) : "r"(addr));
}
__device__ __forceinline__ void ldsm_x4_t(uint32_t& r0, uint32_t& r1, uint32_t& r2,
                                          uint32_t& r3, uint32_t addr) {
    asm volatile("ldmatrix.sync.aligned.m8n8.x4.trans.shared.b16 {%0,%1,%2,%3}, [%4];"
                 : "=r"(r0), "=r"(r1), "=r"(r2), "=r"(r3) : "r"(addr));
}
__device__ __forceinline__ void mma_f16(float* c, const uint32_t* a, const uint32_t* b) {
    asm volatile("mma.sync.aligned.m16n8k16.row.col.f32.f16.f16.f32 "
                 "{%0,%1,%2,%3}, {%4,%5,%6,%7}, {%8,%9}, {%0,%1,%2,%3};"
                 : "+f"(c[0]), "+f"(c[1]), "+f"(c[2]), "+f"(c[3])
                 : "r"(a[0]), "r"(a[1]), "r"(a[2]), "r"(a[3]), "r"(b[0]), "r"(b[1]));
}
__device__ __forceinline__ void cp16(uint32_t dst, const void* src) {
    asm volatile("cp.async.cg.shared.global [%0], [%1], 16;" :: "r"(dst), "l"(src));
}
__device__ __forceinline__ void cp_commit() {
    asm volatile("cp.async.commit_group;");
}
template<int N>
__device__ __forceinline__ void cp_wait() {
    asm volatile("cp.async.wait_group %0;" :: "n"(N));
}
__device__ __forceinline__ float gelu_exact(float v) {
    return 0.5f * v * (1.0f + erff(v * 0.70710678118654752f));
}
__device__ __forceinline__ uint32_t pack_h2(float a, float b) {
    __half2 h = __floats2half2_rn(a, b);
    return *reinterpret_cast<uint32_t*>(&h);
}

// --------------------- fp16 cp.async pipelined GEMM ------------------------
// (validated round 10)
#define ASTRIDE 40
#define BSTRIDE 136
#define A_STG   (128 * ASTRIDE * 2)
#define B_STG   (32 * BSTRIDE * 2)
#define A_SM_OFF 0
#define B_SM_OFF (3 * A_STG)
#define GEMM_SMEM (3 * (A_STG + B_STG))

template<int EPI, typename OutT>
__device__ __forceinline__ void gemm_body(const __half* __restrict__ A,
                                          const __half* __restrict__ W,
                                          const float* __restrict__ bias,
                                          const float* __restrict__ R,
                                          OutT* __restrict__ C,
                                          int N, int K, int m0, int n0,
                                          char* smem) {
    int tid = threadIdx.x;
    int lane = tid & 31;
    int wid = tid >> 5;
    int wr = wid >> 1, wc = wid & 1;

    uint32_t sbase = smem_u32(smem);

    auto load_stage = [&](int s, int k0) {
        uint32_t abase = sbase + A_SM_OFF + s * A_STG;
        uint32_t bbase = sbase + B_SM_OFF + s * B_STG;
#pragma unroll
        for (int it = 0; it < 2; it++) {
            int idx = tid + it * 256;
            int r = idx >> 2, c = idx & 3;
            cp16(abase + (uint32_t)(r * ASTRIDE + c * 8) * 2,
                 &A[(size_t)(m0 + r) * K + k0 + c * 8]);
        }
#pragma unroll
        for (int it = 0; it < 2; it++) {
            int idx = tid + it * 256;
            int r = idx >> 4, c = idx & 15;
            cp16(bbase + (uint32_t)(r * BSTRIDE + c * 8) * 2,
                 &W[(size_t)(k0 + r) * N + n0 + c * 8]);
        }
        cp_commit();
    };

    float acc[2][8][4];
#pragma unroll
    for (int mi = 0; mi < 2; mi++)
#pragma unroll
        for (int n8 = 0; n8 < 8; n8++)
#pragma unroll
            for (int r = 0; r < 4; r++) acc[mi][n8][r] = 0.f;

    int nch = K / 32;
    load_stage(0, 0);
    load_stage(1, 32);

    for (int i = 0; i < nch; i++) {
        int s = i % 3;
        cp_wait<1>();
        __syncthreads();

        uint32_t a_base = sbase + A_SM_OFF + s * A_STG;
        uint32_t b_base = sbase + B_SM_OFF + s * B_STG;
#pragma unroll
        for (int kk = 0; kk < 2; kk++) {
            uint32_t af[2][4];
#pragma unroll
            for (int mi = 0; mi < 2; mi++) {
                int row = wr * 32 + mi * 16 + (lane & 15);
                int col = kk * 16 + (lane >> 4) * 8;
                ldsm_x4(af[mi][0], af[mi][1], af[mi][2], af[mi][3],
                        a_base + (uint32_t)(row * ASTRIDE + col) * 2);
            }
            uint32_t bf[4][4];
#pragma unroll
            for (int ni = 0; ni < 4; ni++) {
                int krow = kk * 16 + (lane & 15);
                int col = wc * 64 + ni * 16 + (lane >> 4) * 8;
                ldsm_x4_t(bf[ni][0], bf[ni][1], bf[ni][2], bf[ni][3],
                          b_base + (uint32_t)(krow * BSTRIDE + col) * 2);
            }
#pragma unroll
            for (int mi = 0; mi < 2; mi++)
#pragma unroll
                for (int ni = 0; ni < 4; ni++) {
                    mma_f16(acc[mi][ni * 2],     af[mi], &bf[ni][0]);
                    mma_f16(acc[mi][ni * 2 + 1], af[mi], &bf[ni][2]);
                }
        }
        __syncthreads();
        if (i + 2 < nch) load_stage((i + 2) % 3, (i + 2) * 32);
        else             cp_commit();   // keep group count uniform (round-8 fix)
    }

#pragma unroll
    for (int mi = 0; mi < 2; mi++) {
        int row0 = m0 + wr * 32 + mi * 16 + (lane >> 2);
#pragma unroll
        for (int n8 = 0; n8 < 8; n8++) {
            int col = n0 + wc * 64 + n8 * 8 + (lane & 3) * 2;
            float2 bv = *(const float2*)&bias[col];
#pragma unroll
            for (int half = 0; half < 2; half++) {
                int row = row0 + half * 8;
                float vx = acc[mi][n8][half * 2 + 0] + bv.x;
                float vy = acc[mi][n8][half * 2 + 1] + bv.y;
                if (EPI == 1) { vx = gelu_exact(vx); vy = gelu_exact(vy); }
                if (EPI == 2) {
                    float2 rv = *(const float2*)&R[(size_t)row * N + col];
                    vx += rv.x; vy += rv.y;
                }
                if (sizeof(OutT) == 2) {
                    *(uint32_t*)&C[(size_t)row * N + col] = pack_h2(vx, vy);
                } else {
                    *(float2*)&C[(size_t)row * N + col] = make_float2(vx, vy);
                }
            }
        }
    }
}

template<int EPI, typename OutT>
__global__ __launch_bounds__(256, 2) void gemm_h(const __half* __restrict__ A,
                                                 const __half* __restrict__ W,
                                                 const float* __restrict__ bias,
                                                 const float* __restrict__ R,
                                                 OutT* __restrict__ C,
                                                 int N, int K) {
    extern __shared__ char smem[];
    gemm_body<EPI, OutT>(A, W, bias, R, C, N, K,
                         blockIdx.y * 128, blockIdx.x * 128, smem);
}

__global__ __launch_bounds__(256, 2) void qkv_h(const __half* __restrict__ A,
                                                const __half* __restrict__ W0,
                                                const __half* __restrict__ W1,
                                                const __half* __restrict__ W2,
                                                const float* __restrict__ b0,
                                                const float* __restrict__ b1,
                                                const float* __restrict__ b2,
                                                __half* __restrict__ o0,
                                                __half* __restrict__ o1,
                                                __half* __restrict__ o2) {
    extern __shared__ char smem[];
    const __half* W = (blockIdx.z == 0) ? W0 : (blockIdx.z == 1) ? W1 : W2;
    const float* bias = (blockIdx.z == 0) ? b0 : (blockIdx.z == 1) ? b1 : b2;
    __half* O = (blockIdx.z == 0) ? o0 : (blockIdx.z == 1) ? o1 : o2;
    gemm_body<0, __half>(A, W, bias, nullptr, O, DIM, DIM,
                         blockIdx.y * 128, blockIdx.x * 128, smem);
}

// ------------------ merged fp32 -> fp16 weight conversion ------------------
#define WSEG  (DIM * DIM / 4)          // 147456 float4 per square weight
#define WBIG  (DIM * DFF / 4)          // 589824 float4 per MLP weight
#define F2H_TOTAL (4 * WSEG + 2 * WBIG)

__global__ __launch_bounds__(256) void f2h_all(const float* __restrict__ Wq,
                                               const float* __restrict__ Wk,
                                               const float* __restrict__ Wv,
                                               const float* __restrict__ Wo,
                                               const float* __restrict__ W1,
                                               const float* __restrict__ W2,
                                               __half* __restrict__ Wqh,
                                               __half* __restrict__ Wkh,
                                               __half* __restrict__ Wvh,
                                               __half* __restrict__ Woh,
                                               __half* __restrict__ W1h,
                                               __half* __restrict__ W2h) {
    int i = blockIdx.x * 256 + threadIdx.x;
    if (i >= F2H_TOTAL) return;
    const float* src;
    __half* dst;
    int off;
    if (i < 4 * WSEG) {
        int seg = i / WSEG;
        off = i - seg * WSEG;
        src = (seg == 0) ? Wq : (seg == 1) ? Wk : (seg == 2) ? Wv : Wo;
        dst = (seg == 0) ? Wqh : (seg == 1) ? Wkh : (seg == 2) ? Wvh : Woh;
    } else {
        int j = i - 4 * WSEG;
        if (j < WBIG) { src = W1; dst = W1h; off = j; }
        else          { src = W2; dst = W2h; off = j - WBIG; }
    }
    float4 v = *(const float4*)&src[(size_t)off * 4];
    uint2 u = {pack_h2(v.x, v.y), pack_h2(v.z, v.w)};
    *(uint2*)&dst[(size_t)off * 4] = u;
}

// ------------------------------ LayerNorm ----------------------------------
__global__ __launch_bounds__(256) void ln_kernel(const float* __restrict__ x,
                                                 const float* __restrict__ g,
                                                 const float* __restrict__ b,
                                                 __half* __restrict__ out) {
    int row = blockIdx.x;
    int tid = threadIdx.x;
    const float* xr = x + (size_t)row * DIM;
    __shared__ float buf[DIM];
    __shared__ float red[256];

    float s = 0.f;
    for (int i = tid; i < DIM; i += 256) { float v = xr[i]; buf[i] = v; s += v; }
    red[tid] = s; __syncthreads();
    for (int off = 128; off > 0; off >>= 1) {
        if (tid < off) red[tid] += red[tid + off];
        __syncthreads();
    }
    float mean = red[0] * (1.0f / DIM);
    __syncthreads();

    float vs = 0.f;
    for (int i = tid; i < DIM; i += 256) { float d = buf[i] - mean; vs += d * d; }
    red[tid] = vs; __syncthreads();
    for (int off = 128; off > 0; off >>= 1) {
        if (tid < off) red[tid] += red[tid + off];
        __syncthreads();
    }
    float rstd = rsqrtf(red[0] * (1.0f / DIM) + LN_EPS);

    __half* orow = out + (size_t)row * DIM;
    for (int i = tid; i < DIM; i += 256)
        orow[i] = __float2half((buf[i] - mean) * rstd * g[i] + b[i]);
}

// ------------- flash attention v2: 128-row Q, cp.async K/V -----------------
// 256 threads = 8 warps; warp w owns query rows [qt*128 + 16w, +16).
#define FPAD      72
#define QS_BYTES  (128 * FPAD * 2)       // 18432
#define KV_STG    (64 * FPAD * 2)        // 9216
#define KS_OFF    QS_BYTES
#define VS_OFF    (QS_BYTES + 2 * KV_STG)
#define FLASH_SMEM (QS_BYTES + 4 * KV_STG)   // 55296

__global__ __launch_bounds__(256) void flash_mma2(const __half* __restrict__ q,
                                                  const __half* __restrict__ k,
                                                  const __half* __restrict__ v,
                                                  __half* __restrict__ ctx) {
    extern __shared__ char smem[];
    int bh = blockIdx.z;
    int b = bh / HEADS, h = bh % HEADS;
    int qt = blockIdx.y;
    const __half* qb = q + (size_t)b * SEQ * DIM + h * HDIM;
    const __half* kb = k + (size_t)b * SEQ * DIM + h * HDIM;
    const __half* vb = v + (size_t)b * SEQ * DIM + h * HDIM;
    __half* ob = ctx + (size_t)b * SEQ * DIM + h * HDIM;

    uint32_t sbase = smem_u32(smem);
    int tid = threadIdx.x;
    int lane = tid & 31;
    int w = tid >> 5;

    // load Q tile (128 x 64 halves) — plain loads, happens once
#pragma unroll
    for (int it = 0; it < 4; it++) {
        int idx = tid + it * 256;        // 1024 uint4 slots
        int r = idx >> 3, c8 = idx & 7;
        *(uint4*)(smem + (uint32_t)(r * FPAD + c8 * 8) * 2) =
            *(const uint4*)&qb[(size_t)(qt * 128 + r) * DIM + c8 * 8];
    }

    // K/V stage loader (cp.async, double buffered)
    auto load_kv = [&](int buf, int t) {
        uint32_t kbase = sbase + KS_OFF + buf * KV_STG;
        uint32_t vbase = sbase + VS_OFF + buf * KV_STG;
#pragma unroll
        for (int it = 0; it < 2; it++) {
            int idx = tid + it * 256;    // 512 slots
            int r = idx >> 3, c8 = idx & 7;
            cp16(kbase + (uint32_t)(r * FPAD + c8 * 8) * 2,
                 &kb[(size_t)(t * 64 + r) * DIM + c8 * 8]);
        }
#pragma unroll
        for (int it = 0; it < 2; it++) {
            int idx = tid + it * 256;
            int r = idx >> 3, c8 = idx & 7;
            cp16(vbase + (uint32_t)(r * FPAD + c8 * 8) * 2,
                 &vb[(size_t)(t * 64 + r) * DIM + c8 * 8]);
        }
        cp_commit();
    };

    load_kv(0, 0);
    __syncthreads();   // Q visible to all warps

    // hoist Q fragments
    uint32_t qf[4][4];
#pragma unroll
    for (int kk = 0; kk < 4; kk++) {
        int row = w * 16 + (lane & 15);
        int col = kk * 16 + (lane >> 4) * 8;
        ldsm_x4(qf[kk][0], qf[kk][1], qf[kk][2], qf[kk][3],
                sbase + (uint32_t)(row * FPAD + col) * 2);
    }

    float m0 = -1e30f, m1 = -1e30f, l0 = 0.f, l1 = 0.f;
    float o[8][4];
#pragma unroll
    for (int j = 0; j < 8; j++)
#pragma unroll
        for (int r = 0; r < 4; r++) o[j][r] = 0.f;

    for (int t = 0; t < SEQ / 64; t++) {
        int buf = t & 1;
        if (t + 1 < SEQ / 64) { load_kv(buf ^ 1, t + 1); cp_wait<1>(); }
        else                  { cp_wait<0>(); }
        __syncthreads();

        uint32_t kt = sbase + KS_OFF + buf * KV_STG;
        uint32_t vt = sbase + VS_OFF + buf * KV_STG;

        // S = Q K^T
        float s[8][4];
#pragma unroll
        for (int j = 0; j < 8; j++)
#pragma unroll
            for (int r = 0; r < 4; r++) s[j][r] = 0.f;
#pragma unroll
        for (int kk = 0; kk < 4; kk++) {
#pragma unroll
            for (int nt = 0; nt < 4; nt++) {
                int krow = nt * 16 + (lane & 7) + ((lane >> 4) << 3);
                int kcol = kk * 16 + ((lane >> 3) & 1) * 8;
                uint32_t kf[4];
                ldsm_x4(kf[0], kf[1], kf[2], kf[3],
                        kt + (uint32_t)(krow * FPAD + kcol) * 2);
                mma_f16(s[nt * 2],     qf[kk], &kf[0]);
                mma_f16(s[nt * 2 + 1], qf[kk], &kf[2]);
            }
        }

        // online softmax
        float tm0 = -1e30f, tm1 = -1e30f;
#pragma unroll
        for (int j = 0; j < 8; j++) {
#pragma unroll
            for (int r = 0; r < 4; r++) s[j][r] *= 0.125f;
            tm0 = fmaxf(tm0, fmaxf(s[j][0], s[j][1]));
            tm1 = fmaxf(tm1, fmaxf(s[j][2], s[j][3]));
        }
#pragma unroll
        for (int mask = 1; mask <= 2; mask <<= 1) {
            tm0 = fmaxf(tm0, __shfl_xor_sync(0xffffffffu, tm0, mask));
            tm1 = fmaxf(tm1, __shfl_xor_sync(0xffffffffu, tm1, mask));
        }
        float mn0 = fmaxf(m0, tm0), mn1 = fmaxf(m1, tm1);
        float sc0 = __expf(m0 - mn0), sc1 = __expf(m1 - mn1);
        m0 = mn0; m1 = mn1;

        uint32_t ph0[8], ph1[8];
        float rs0 = 0.f, rs1 = 0.f;
#pragma unroll
        for (int j = 0; j < 8; j++) {
            float p0 = __expf(s[j][0] - mn0), p1 = __expf(s[j][1] - mn0);
            float p2 = __expf(s[j][2] - mn1), p3 = __expf(s[j][3] - mn1);
            rs0 += p0 + p1; rs1 += p2 + p3;
            ph0[j] = pack_h2(p0, p1);
            ph1[j] = pack_h2(p2, p3);
        }
#pragma unroll
        for (int mask = 1; mask <= 2; mask <<= 1) {
            rs0 += __shfl_xor_sync(0xffffffffu, rs0, mask);
            rs1 += __shfl_xor_sync(0xffffffffu, rs1, mask);
        }
        l0 = l0 * sc0 + rs0;
        l1 = l1 * sc1 + rs1;
#pragma unroll
        for (int j = 0; j < 8; j++) {
            o[j][0] *= sc0; o[j][1] *= sc0;
            o[j][2] *= sc1; o[j][3] *= sc1;
        }

        // O += P @ V (FA-2 register repack for A)
#pragma unroll
        for (int kk = 0; kk < 4; kk++) {
            uint32_t a[4] = {ph0[2 * kk], ph1[2 * kk], ph0[2 * kk + 1], ph1[2 * kk + 1]};
#pragma unroll
            for (int nt = 0; nt < 4; nt++) {
                int vrow = kk * 16 + (lane & 15);
                int vcol = nt * 16 + (lane >> 4) * 8;
                uint32_t vf[4];
                ldsm_x4_t(vf[0], vf[1], vf[2], vf[3],
                          vt + (uint32_t)(vrow * FPAD + vcol) * 2);
                mma_f16(o[nt * 2],     a, &vf[0]);
                mma_f16(o[nt * 2 + 1], a, &vf[2]);
            }
        }
        __syncthreads();   // all warps done with buf before next-next load
    }

    float inv0 = 1.0f / l0, inv1 = 1.0f / l1;
    int row0 = qt * 128 + w * 16 + (lane >> 2);
    int row1 = row0 + 8;
#pragma unroll
    for (int j = 0; j < 8; j++) {
        int col = (j >> 1) * 16 + (j & 1) * 8 + (lane & 3) * 2;
        *(uint32_t*)&ob[(size_t)row0 * DIM + col] = pack_h2(o[j][0] * inv0, o[j][1] * inv0);
        *(uint32_t*)&ob[(size_t)row1 * DIM + col] = pack_h2(o[j][2] * inv1, o[j][3] * inv1);
    }
}

// ------------------------------ launcher -----------------------------------
extern "C" void kernel_launch(void* const* d_in, const int* in_sizes, int n_in,
                              void* d_out, int out_size) {
    (void)in_sizes; (void)n_in; (void)out_size;
    const float* x     = (const float*)d_in[0];
    const float* ln1_g = (const float*)d_in[1];
    const float* ln1_b = (const float*)d_in[2];
    const float* Wq    = (const float*)d_in[3];
    const float* bq    = (const float*)d_in[4];
    const float* Wk    = (const float*)d_in[5];
    const float* bk    = (const float*)d_in[6];
    const float* Wv    = (const float*)d_in[7];
    const float* bv    = (const float*)d_in[8];
    const float* Wo    = (const float*)d_in[9];
    const float* bo    = (const float*)d_in[10];
    const float* ln2_g = (const float*)d_in[11];
    const float* ln2_b = (const float*)d_in[12];
    const float* W1    = (const float*)d_in[13];
    const float* b1    = (const float*)d_in[14];
    const float* W2    = (const float*)d_in[15];
    const float* b2    = (const float*)d_in[16];
    float* out = (float*)d_out;

    __half *xnh, *qh, *kh, *vh, *ctxh, *xn2h, *h1h;
    __half *Wqh, *Wkh, *Wvh, *Woh, *W1h, *W2h;
    float *x1;
    cudaGetSymbolAddress((void**)&xnh,  g_xnh);
    cudaGetSymbolAddress((void**)&qh,   g_qh);
    cudaGetSymbolAddress((void**)&kh,   g_kh);
    cudaGetSymbolAddress((void**)&vh,   g_vh);
    cudaGetSymbolAddress((void**)&ctxh, g_ctxh);
    cudaGetSymbolAddress((void**)&x1,   g_x1);
    cudaGetSymbolAddress((void**)&xn2h, g_xn2h);
    cudaGetSymbolAddress((void**)&h1h,  g_h1h);
    cudaGetSymbolAddress((void**)&Wqh,  g_Wqh);
    cudaGetSymbolAddress((void**)&Wkh,  g_Wkh);
    cudaGetSymbolAddress((void**)&Wvh,  g_Wvh);
    cudaGetSymbolAddress((void**)&Woh,  g_Woh);
    cudaGetSymbolAddress((void**)&W1h,  g_W1h);
    cudaGetSymbolAddress((void**)&W2h,  g_W2h);

    cudaFuncSetAttribute(gemm_h<0, __half>, cudaFuncAttributeMaxDynamicSharedMemorySize, GEMM_SMEM);
    cudaFuncSetAttribute(gemm_h<1, __half>, cudaFuncAttributeMaxDynamicSharedMemorySize, GEMM_SMEM);
    cudaFuncSetAttribute(gemm_h<2, float>,  cudaFuncAttributeMaxDynamicSharedMemorySize, GEMM_SMEM);
    cudaFuncSetAttribute(qkv_h, cudaFuncAttributeMaxDynamicSharedMemorySize, GEMM_SMEM);
    cudaFuncSetAttribute(flash_mma2, cudaFuncAttributeMaxDynamicSharedMemorySize, FLASH_SMEM);

    // 0. convert all weights to fp16 (single launch)
    f2h_all<<<(F2H_TOTAL + 255) / 256, 256>>>(Wq, Wk, Wv, Wo, W1, W2,
                                              Wqh, Wkh, Wvh, Woh, W1h, W2h);

    // 1. LN1 -> fp16
    ln_kernel<<<TOKENS, 256>>>(x, ln1_g, ln1_b, xnh);

    // 2. fused QKV (fp16 in/out)
    qkv_h<<<dim3(DIM / 128, TOKENS / 128, 3), 256, GEMM_SMEM>>>(
        xnh, Wqh, Wkh, Wvh, bq, bk, bv, qh, kh, vh);

    // 3. flash attention v2 -> fp16 ctx
    flash_mma2<<<dim3(1, SEQ / 128, BATCH * HEADS), 256, FLASH_SMEM>>>(qh, kh, vh, ctxh);

    // 4. Wo + residual(x) -> fp32 x1
    gemm_h<2, float><<<dim3(DIM / 128, TOKENS / 128), 256, GEMM_SMEM>>>(
        ctxh, Woh, bo, x, x1, DIM, DIM);

    // 5. LN2 -> fp16
    ln_kernel<<<TOKENS, 256>>>(x1, ln2_g, ln2_b, xn2h);

    // 6. W1 + GELU -> fp16 h1
    gemm_h<1, __half><<<dim3(DFF / 128, TOKENS / 128), 256, GEMM_SMEM>>>(
        xn2h, W1h, b1, nullptr, h1h, DFF, DIM);

    // 7. W2 + residual(x1) -> fp32 out
    gemm_h<2, float><<<dim3(DIM / 128, TOKENS / 128), 256, GEMM_SMEM>>>(
        h1h, W2h, b2, x1, out, DIM, DFF);
}